// round 6
// baseline (speedup 1.0000x reference)
#include <cuda_runtime.h>
#include <cuda_bf16.h>
#include <math.h>
#include <stdint.h>

#define D_MODEL 768
#define N_HEADS 12
#define D_KH    64
#define B_      2
#define S_      2048
#define M_TOT   (B_ * S_)
#define BH_     (B_ * N_HEADS)
#define LN_EPS  1e-5f
#define NELEM   ((size_t)M_TOT * D_MODEL)
#define WELEM   ((size_t)D_MODEL * D_MODEL)
#define EELEM   ((size_t)BH_ * S_ * S_)

// ---------------- scratch (allocation-free: __device__ globals) ----------------
__device__ uint16_t g_inqh[NELEM], g_inql[NELEM];
__device__ uint16_t g_inkh[NELEM], g_inkl[NELEM];
__device__ uint16_t g_invh[NELEM], g_invl[NELEM];
__device__ uint16_t g_wqh[WELEM], g_wql[WELEM];
__device__ uint16_t g_wkh[WELEM], g_wkl[WELEM];
__device__ uint16_t g_wvh[WELEM], g_wvl[WELEM];
__device__ uint16_t g_woh[WELEM], g_wol[WELEM];
__device__ uint16_t g_Qh[NELEM], g_Ql[NELEM];
__device__ uint16_t g_Kh[NELEM], g_Kl[NELEM];
__device__ uint16_t g_Vh[NELEM], g_Vl[NELEM];
__device__ uint16_t g_Oh[NELEM], g_Ol[NELEM];
__device__ float    g_P[NELEM];
__device__ uint16_t g_Eh[EELEM], g_El[EELEM];     // exp(scores), split bf16
__device__ float    g_rs[(size_t)BH_ * S_];       // row sums of E

// ======================= helpers =======================
__device__ __forceinline__ uint32_t smem_u32(const void* p) {
    uint32_t a;
    asm("{ .reg .u64 t; cvta.to.shared.u64 t, %1; cvt.u32.u64 %0, t; }"
        : "=r"(a) : "l"(p));
    return a;
}
__device__ __forceinline__ void ldm_x4(uint32_t* r, uint32_t addr) {
    asm volatile("ldmatrix.sync.aligned.m8n8.x4.shared.b16 {%0,%1,%2,%3}, [%4];"
                 : "=r"(r[0]), "=r"(r[1]), "=r"(r[2]), "=r"(r[3]) : "r"(addr));
}
__device__ __forceinline__ void ldm_x2(uint32_t* r, uint32_t addr) {
    asm volatile("ldmatrix.sync.aligned.m8n8.x2.shared.b16 {%0,%1}, [%2];"
                 : "=r"(r[0]), "=r"(r[1]) : "r"(addr));
}
__device__ __forceinline__ void ldm_x2_trans(uint32_t* r, uint32_t addr) {
    asm volatile("ldmatrix.sync.aligned.m8n8.x2.trans.shared.b16 {%0,%1}, [%2];"
                 : "=r"(r[0]), "=r"(r[1]) : "r"(addr));
}
__device__ __forceinline__ void mma_bf16(float* c, const uint32_t* a, const uint32_t* b) {
    asm volatile(
        "mma.sync.aligned.m16n8k16.row.col.f32.bf16.bf16.f32 "
        "{%0,%1,%2,%3}, {%4,%5,%6,%7}, {%8,%9}, {%0,%1,%2,%3};"
        : "+f"(c[0]), "+f"(c[1]), "+f"(c[2]), "+f"(c[3])
        : "r"(a[0]), "r"(a[1]), "r"(a[2]), "r"(a[3]), "r"(b[0]), "r"(b[1]));
}
__device__ __forceinline__ void cp16(uint32_t s, const void* g) {
    asm volatile("cp.async.cg.shared.global [%0], [%1], 16;" :: "r"(s), "l"(g));
}
#define CP_COMMIT() asm volatile("cp.async.commit_group;")
#define CP_WAIT0()  asm volatile("cp.async.wait_group 0;")
#define CP_WAIT1()  asm volatile("cp.async.wait_group 1;")

__device__ __forceinline__ uint32_t pack2(__nv_bfloat16 a, __nv_bfloat16 b) {
    return ((uint32_t)__bfloat16_as_ushort(b) << 16) | (uint32_t)__bfloat16_as_ushort(a);
}
__device__ __forceinline__ void split4(float4 v, uint2& hi, uint2& lo) {
    __nv_bfloat16 h0 = __float2bfloat16(v.x), h1 = __float2bfloat16(v.y);
    __nv_bfloat16 h2 = __float2bfloat16(v.z), h3 = __float2bfloat16(v.w);
    hi = make_uint2(pack2(h0, h1), pack2(h2, h3));
    __nv_bfloat16 l0 = __float2bfloat16(v.x - __bfloat162float(h0));
    __nv_bfloat16 l1 = __float2bfloat16(v.y - __bfloat162float(h1));
    __nv_bfloat16 l2 = __float2bfloat16(v.z - __bfloat162float(h2));
    __nv_bfloat16 l3 = __float2bfloat16(v.w - __bfloat162float(h3));
    lo = make_uint2(pack2(l0, l1), pack2(l2, l3));
}
__device__ __forceinline__ void split2(float x, float y, uint32_t& hi, uint32_t& lo) {
    __nv_bfloat16 h0 = __float2bfloat16(x), h1 = __float2bfloat16(y);
    hi = pack2(h0, h1);
    lo = pack2(__float2bfloat16(x - __bfloat162float(h0)),
               __float2bfloat16(y - __bfloat162float(h1)));
}
// bf16-pair u32 -> two fp32
__device__ __forceinline__ void unpack2(uint32_t u, float& a, float& b) {
    a = __uint_as_float(u << 16);
    b = __uint_as_float(u & 0xffff0000u);
}

// ======================= small kernels =======================
__global__ void split_kernel(const float4* __restrict__ in,
                             uint2* __restrict__ hi, uint2* __restrict__ lo)
{
    int i = blockIdx.x * 256 + threadIdx.x;
    uint2 h, l;
    split4(in[i], h, l);
    hi[i] = h; lo[i] = l;
}

__global__ void zero_rs_kernel(float4* __restrict__ rs)
{
    rs[blockIdx.x * 256 + threadIdx.x] = make_float4(0.f, 0.f, 0.f, 0.f);
}

// zero the strictly-masked upper tiles of attn
__global__ void zerofill_kernel(float* __restrict__ attn)
{
    const int qt = blockIdx.x, kt = blockIdx.y, bh = blockIdx.z;
    if (kt <= qt) return;
    const int tid = threadIdx.x;
    float4 z = make_float4(0.f, 0.f, 0.f, 0.f);
    float4* o4 = (float4*)(attn + ((size_t)bh * S_ + qt * 128) * S_ + kt * 128);
    #pragma unroll
    for (int i = 0; i < 16; i++) {
        int f = tid + i * 256;
        int r = f >> 5, c = f & 31;
        o4[(size_t)r * (S_ / 4) + c] = z;
    }
}

#define LDA 40
#define LDV 72

// =====================================================================
// Pipelined split-bf16 GEMM (NT): C = A @ W^T + bias. (as R5)
// =====================================================================
template<bool SPLIT_OUT>
__global__ void __launch_bounds__(256)
gemm_s(const uint16_t* __restrict__ Ahg, const uint16_t* __restrict__ Alg,
       const uint16_t* __restrict__ Whg, const uint16_t* __restrict__ Wlg,
       const float* __restrict__ bias,
       uint16_t* __restrict__ Ch, uint16_t* __restrict__ Cl,
       float* __restrict__ Cf)
{
    extern __shared__ __align__(16) char sm[];
    const uint32_t sb = smem_u32(sm);
    const int tid = threadIdx.x, wid = tid >> 5, lane = tid & 31;
    const int m0 = blockIdx.x * 128, n0 = blockIdx.y * 128;
    const int wm = (wid & 1) * 64, wn = (wid >> 1) * 32;

    float acc[4][4][4] = {};
    {
        #pragma unroll
        for (int i = 0; i < 2; i++) {
            int f = tid + i * 256;
            int r = f >> 2, c8 = (f & 3) * 8;
            uint32_t so = sb + (uint32_t)(r * LDA + c8) * 2;
            size_t ga = (size_t)(m0 + r) * 768 + c8;
            size_t gb = (size_t)(n0 + r) * 768 + c8;
            cp16(so,          Ahg + ga);
            cp16(so + 10240u, Alg + ga);
            cp16(so + 20480u, Whg + gb);
            cp16(so + 30720u, Wlg + gb);
        }
        CP_COMMIT();
    }
    for (int c = 0; c < 24; c++) {
        const int st = c & 1;
        if (c < 23) {
            const int k0 = (c + 1) * 32;
            const uint32_t stb = sb + (uint32_t)(st ^ 1) * 40960u;
            #pragma unroll
            for (int i = 0; i < 2; i++) {
                int f = tid + i * 256;
                int r = f >> 2, c8 = (f & 3) * 8;
                uint32_t so = stb + (uint32_t)(r * LDA + c8) * 2;
                size_t ga = (size_t)(m0 + r) * 768 + k0 + c8;
                size_t gb = (size_t)(n0 + r) * 768 + k0 + c8;
                cp16(so,          Ahg + ga);
                cp16(so + 10240u, Alg + ga);
                cp16(so + 20480u, Whg + gb);
                cp16(so + 30720u, Wlg + gb);
            }
            CP_COMMIT();
            CP_WAIT1();
        } else {
            CP_WAIT0();
        }
        __syncthreads();
        const uint32_t base = sb + (uint32_t)st * 40960u;
        #pragma unroll
        for (int ks = 0; ks < 2; ks++) {
            uint32_t ah[4][4], al[4][4];
            const int arow = wm + (lane & 7) + ((lane >> 3) & 1) * 8;
            const int acol = ks * 16 + (lane >> 4) * 8;
            #pragma unroll
            for (int mt = 0; mt < 4; mt++) {
                uint32_t off = (uint32_t)((arow + mt * 16) * LDA + acol) * 2;
                ldm_x4(ah[mt], base + off);
                ldm_x4(al[mt], base + 10240u + off);
            }
            const int brow = wn + (lane & 7);
            const int bcol = ks * 16 + ((lane >> 3) & 1) * 8;
            #pragma unroll
            for (int nt = 0; nt < 4; nt++) {
                uint32_t off = (uint32_t)((brow + nt * 8) * LDA + bcol) * 2;
                uint32_t bh2[2], bl2[2];
                ldm_x2(bh2, base + 20480u + off);
                ldm_x2(bl2, base + 30720u + off);
                #pragma unroll
                for (int mt = 0; mt < 4; mt++) {
                    mma_bf16(acc[mt][nt], ah[mt], bh2);
                    mma_bf16(acc[mt][nt], ah[mt], bl2);
                    mma_bf16(acc[mt][nt], al[mt], bh2);
                }
            }
        }
        __syncthreads();
    }
    #pragma unroll
    for (int mt = 0; mt < 4; mt++) {
        const int m = m0 + wm + mt * 16 + (lane >> 2);
        #pragma unroll
        for (int nt = 0; nt < 4; nt++) {
            const int n = n0 + wn + nt * 8 + (lane & 3) * 2;
            float2 bv = *(const float2*)&bias[n];
            float f0 = acc[mt][nt][0] + bv.x, f1 = acc[mt][nt][1] + bv.y;
            float f2 = acc[mt][nt][2] + bv.x, f3 = acc[mt][nt][3] + bv.y;
            if (SPLIT_OUT) {
                uint32_t hi, lo;
                split2(f0, f1, hi, lo);
                *(uint32_t*)&Ch[(size_t)m * 768 + n] = hi;
                *(uint32_t*)&Cl[(size_t)m * 768 + n] = lo;
                split2(f2, f3, hi, lo);
                *(uint32_t*)&Ch[(size_t)(m + 8) * 768 + n] = hi;
                *(uint32_t*)&Cl[(size_t)(m + 8) * 768 + n] = lo;
            } else {
                *(float2*)&Cf[(size_t)m * 768 + n]       = make_float2(f0, f1);
                *(float2*)&Cf[(size_t)(m + 8) * 768 + n] = make_float2(f2, f3);
            }
        }
    }
}

// =====================================================================
// scores_exp: E = exp(0.125 * Q.K^T) with causal mask (masked -> 0),
// writes split bf16 E planes, atomic row sums. Only kt<=qt tiles.
// =====================================================================
__global__ void __launch_bounds__(256)
scores_exp(const uint16_t* __restrict__ Qh, const uint16_t* __restrict__ Ql,
           const uint16_t* __restrict__ Kh, const uint16_t* __restrict__ Kl,
           uint16_t* __restrict__ Eh, uint16_t* __restrict__ El,
           float* __restrict__ rs)
{
    const int qt = blockIdx.x, kt = blockIdx.y, bh = blockIdx.z;
    if (kt > qt) return;
    const int q0 = qt * 128, k0 = kt * 128;
    const int tid = threadIdx.x;

    extern __shared__ __align__(16) char sm[];
    const uint32_t sb = smem_u32(sm);
    const int wid = tid >> 5, lane = tid & 31;
    const int b = bh / N_HEADS, h = bh % N_HEADS;
    const int wm = (wid & 1) * 64, wn = (wid >> 1) * 32;
    const size_t qbase = (size_t)(b * S_ + q0) * 768 + h * 64;
    const size_t kbase = (size_t)(b * S_ + k0) * 768 + h * 64;

    #pragma unroll
    for (int i = 0; i < 4; i++) {
        int f = tid + i * 256;
        int r = f >> 3, c8 = (f & 7) * 8;
        uint32_t so = sb + (uint32_t)(r * LDV + c8) * 2;
        size_t gq = qbase + (size_t)r * 768 + c8;
        size_t gk = kbase + (size_t)r * 768 + c8;
        cp16(so,          Qh + gq);
        cp16(so + 18432u, Ql + gq);
        cp16(so + 36864u, Kh + gk);
        cp16(so + 55296u, Kl + gk);
    }
    CP_COMMIT(); CP_WAIT0();
    __syncthreads();

    float acc[4][4][4] = {};
    #pragma unroll
    for (int ks = 0; ks < 4; ks++) {
        uint32_t ah[4][4], al[4][4];
        const int arow = wm + (lane & 7) + ((lane >> 3) & 1) * 8;
        const int acol = ks * 16 + (lane >> 4) * 8;
        #pragma unroll
        for (int mt = 0; mt < 4; mt++) {
            uint32_t off = (uint32_t)((arow + mt * 16) * LDV + acol) * 2;
            ldm_x4(ah[mt], sb + off);
            ldm_x4(al[mt], sb + 18432u + off);
        }
        const int brow = wn + (lane & 7);
        const int bcol = ks * 16 + ((lane >> 3) & 1) * 8;
        #pragma unroll
        for (int nt = 0; nt < 4; nt++) {
            uint32_t off = (uint32_t)((brow + nt * 8) * LDV + bcol) * 2;
            uint32_t bh2[2], bl2[2];
            ldm_x2(bh2, sb + 36864u + off);
            ldm_x2(bl2, sb + 55296u + off);
            #pragma unroll
            for (int mt = 0; mt < 4; mt++) {
                mma_bf16(acc[mt][nt], ah[mt], bh2);
                mma_bf16(acc[mt][nt], ah[mt], bl2);
                mma_bf16(acc[mt][nt], al[mt], bh2);
            }
        }
    }

    // epilogue: exp + mask + split-store + row-sum atomics
    #pragma unroll
    for (int mt = 0; mt < 4; mt++) {
        const int qr0 = q0 + wm + mt * 16 + (lane >> 2);
        const int qr1 = qr0 + 8;
        float rsum0 = 0.f, rsum1 = 0.f;
        #pragma unroll
        for (int nt = 0; nt < 4; nt++) {
            const int kc = k0 + wn + nt * 8 + (lane & 3) * 2;
            float e0 = (kc     <= qr0) ? __expf(acc[mt][nt][0] * 0.125f) : 0.f;
            float e1 = (kc + 1 <= qr0) ? __expf(acc[mt][nt][1] * 0.125f) : 0.f;
            float e2 = (kc     <= qr1) ? __expf(acc[mt][nt][2] * 0.125f) : 0.f;
            float e3 = (kc + 1 <= qr1) ? __expf(acc[mt][nt][3] * 0.125f) : 0.f;
            rsum0 += e0 + e1;
            rsum1 += e2 + e3;
            uint32_t hi, lo;
            size_t i0 = ((size_t)bh * S_ + qr0) * S_ + kc;
            size_t i1 = ((size_t)bh * S_ + qr1) * S_ + kc;
            split2(e0, e1, hi, lo);
            *(uint32_t*)&Eh[i0] = hi; *(uint32_t*)&El[i0] = lo;
            split2(e2, e3, hi, lo);
            *(uint32_t*)&Eh[i1] = hi; *(uint32_t*)&El[i1] = lo;
        }
        rsum0 += __shfl_xor_sync(0xffffffff, rsum0, 1);
        rsum0 += __shfl_xor_sync(0xffffffff, rsum0, 2);
        rsum1 += __shfl_xor_sync(0xffffffff, rsum1, 1);
        rsum1 += __shfl_xor_sync(0xffffffff, rsum1, 2);
        if ((lane & 3) == 0) {
            atomicAdd(&rs[(size_t)bh * S_ + qr0], rsum0);
            atomicAdd(&rs[(size_t)bh * S_ + qr1], rsum1);
        }
    }
}

// =====================================================================
// pv: O = (E @ V) / rowsum ; also writes normalized fp32 attn (causal half).
// E pre-split bf16; V pre-split; K-chunks of 32 up to (qt+1)*128.
// =====================================================================
__global__ void __launch_bounds__(256)
pv_s(const uint16_t* __restrict__ Eh, const uint16_t* __restrict__ El,
     const float* __restrict__ rs,
     const uint16_t* __restrict__ Vhg, const uint16_t* __restrict__ Vlg,
     float* __restrict__ attn,
     uint16_t* __restrict__ Oh, uint16_t* __restrict__ Ol)
{
    __shared__ __align__(16) uint16_t Ph[128][LDA], Pl[128][LDA];
    __shared__ __align__(16) uint16_t Vh_s[32][LDV], Vl_s[32][LDV];
    __shared__ float inv_s[128];
    const int tid = threadIdx.x, wid = tid >> 5, lane = tid & 31;
    const int qt = gridDim.x - 1 - blockIdx.x;
    const int bh = blockIdx.y;
    const int b = bh / N_HEADS, h = bh % N_HEADS;
    const int q0 = qt * 128;
    const int wm = (wid & 3) * 32, wn = (wid >> 2) * 32;
    const uint32_t pHb = smem_u32(Ph), pLb = smem_u32(Pl);
    const uint32_t vHb = smem_u32(Vh_s), vLb = smem_u32(Vl_s);

    if (tid < 128)
        inv_s[tid] = 1.0f / rs[(size_t)bh * S_ + q0 + tid];
    const size_t vbase = (size_t)(b * S_) * 768 + h * 64;
    const size_t ebase = ((size_t)bh * S_ + q0) * S_;
    __syncthreads();

    float acc[2][4][4] = {};
    const int n_chunks = 4 * (qt + 1);

    for (int c = 0; c < n_chunks; c++) {
        const int k0 = c * 32;
        {
            int r = tid >> 3, c8 = (tid & 7) * 8;
            uint32_t so = (uint32_t)(r * LDV + c8) * 2;
            size_t gv = vbase + (size_t)(k0 + r) * 768 + c8;
            cp16(vHb + so, Vhg + gv);
            cp16(vLb + so, Vlg + gv);
            CP_COMMIT();
        }
        // E chunk: load split pair, write normalized attn, stage to smem
        #pragma unroll
        for (int i = 0; i < 4; i++) {
            int f = tid + i * 256;
            int r = f >> 3, c4 = (f & 7) * 4;
            size_t gi = ebase + (size_t)r * S_ + k0 + c4;
            uint2 hi = *(const uint2*)&Eh[gi];
            uint2 lo = *(const uint2*)&El[gi];
            *(uint2*)&Ph[r][c4] = hi;
            *(uint2*)&Pl[r][c4] = lo;
            float h0, h1, h2, h3, l0, l1, l2, l3;
            unpack2(hi.x, h0, h1); unpack2(hi.y, h2, h3);
            unpack2(lo.x, l0, l1); unpack2(lo.y, l2, l3);
            const float inv = inv_s[r];
            *(float4*)&attn[gi] = make_float4((h0 + l0) * inv, (h1 + l1) * inv,
                                              (h2 + l2) * inv, (h3 + l3) * inv);
        }
        CP_WAIT0();
        __syncthreads();
        #pragma unroll
        for (int ks = 0; ks < 2; ks++) {
            uint32_t ph[2][4], pl[2][4];
            const int arow = wm + (lane & 7) + ((lane >> 3) & 1) * 8;
            const int acol = ks * 16 + (lane >> 4) * 8;
            #pragma unroll
            for (int mt = 0; mt < 2; mt++) {
                uint32_t off = (uint32_t)((arow + mt * 16) * LDA + acol) * 2;
                ldm_x4(ph[mt], pHb + off);
                ldm_x4(pl[mt], pLb + off);
            }
            const int krow = ks * 16 + ((lane >> 3) & 1) * 8 + (lane & 7);
            #pragma unroll
            for (int nt = 0; nt < 4; nt++) {
                uint32_t off = (uint32_t)(krow * LDV + wn + nt * 8) * 2;
                uint32_t vh2[2], vl2[2];
                ldm_x2_trans(vh2, vHb + off);
                ldm_x2_trans(vl2, vLb + off);
                #pragma unroll
                for (int mt = 0; mt < 2; mt++) {
                    mma_bf16(acc[mt][nt], ph[mt], vh2);
                    mma_bf16(acc[mt][nt], ph[mt], vl2);
                    mma_bf16(acc[mt][nt], pl[mt], vh2);
                }
            }
        }
        __syncthreads();
    }
    #pragma unroll
    for (int mt = 0; mt < 2; mt++) {
        const int lr = wm + mt * 16 + (lane >> 2);
        const int qrow = q0 + lr;
        const float inv0 = inv_s[lr], inv1 = inv_s[lr + 8];
        const size_t r0 = (size_t)(b * S_ + qrow) * 768 + h * 64;
        const size_t r1 = (size_t)(b * S_ + qrow + 8) * 768 + h * 64;
        #pragma unroll
        for (int nt = 0; nt < 4; nt++) {
            const int n = wn + nt * 8 + (lane & 3) * 2;
            uint32_t hi, lo;
            split2(acc[mt][nt][0] * inv0, acc[mt][nt][1] * inv0, hi, lo);
            *(uint32_t*)&Oh[r0 + n] = hi;
            *(uint32_t*)&Ol[r0 + n] = lo;
            split2(acc[mt][nt][2] * inv1, acc[mt][nt][3] * inv1, hi, lo);
            *(uint32_t*)&Oh[r1 + n] = hi;
            *(uint32_t*)&Ol[r1 + n] = lo;
        }
    }
}

// =====================================================================
// Residual + LayerNorm, float4, 192 threads.
// =====================================================================
__global__ void ln_kernel(const float* __restrict__ resid,
                          const float* __restrict__ P,
                          const float* __restrict__ gamma,
                          const float* __restrict__ beta,
                          float* __restrict__ out)
{
    const int m = blockIdx.x;
    const int tid = threadIdx.x;
    const int lane = tid & 31, wid = tid >> 5;
    __shared__ float red[6];

    const float4* r4 = (const float4*)(resid + (size_t)m * D_MODEL);
    const float4* p4 = (const float4*)(P + (size_t)m * D_MODEL);
    float4 a = r4[tid], b = p4[tid];
    float4 x = make_float4(a.x + b.x, a.y + b.y, a.z + b.z, a.w + b.w);

    float s = x.x + x.y + x.z + x.w;
    #pragma unroll
    for (int sh = 16; sh > 0; sh >>= 1)
        s += __shfl_xor_sync(0xffffffff, s, sh);
    if (lane == 0) red[wid] = s;
    __syncthreads();
    s = red[0] + red[1] + red[2] + red[3] + red[4] + red[5];
    const float mu = s * (1.0f / D_MODEL);
    __syncthreads();

    float4 d = make_float4(x.x - mu, x.y - mu, x.z - mu, x.w - mu);
    float v = d.x * d.x + d.y * d.y + d.z * d.z + d.w * d.w;
    #pragma unroll
    for (int sh = 16; sh > 0; sh >>= 1)
        v += __shfl_xor_sync(0xffffffff, v, sh);
    if (lane == 0) red[wid] = v;
    __syncthreads();
    v = red[0] + red[1] + red[2] + red[3] + red[4] + red[5];
    const float rstd = rsqrtf(v * (1.0f / D_MODEL) + LN_EPS);

    float4 g = ((const float4*)gamma)[tid];
    float4 be = ((const float4*)beta)[tid];
    float4 o = make_float4(d.x * rstd * g.x + be.x,
                           d.y * rstd * g.y + be.y,
                           d.z * rstd * g.z + be.z,
                           d.w * rstd * g.w + be.w);
    ((float4*)(out + (size_t)m * D_MODEL))[tid] = o;
}

// =====================================================================
extern "C" void kernel_launch(void* const* d_in, const int* in_sizes, int n_in,
                              void* d_out, int out_size)
{
    const float* q     = (const float*)d_in[0];
    const float* k     = (const float*)d_in[1];
    const float* v     = (const float*)d_in[2];
    const float* Wq    = (const float*)d_in[4];
    const float* bq    = (const float*)d_in[5];
    const float* Wk    = (const float*)d_in[6];
    const float* bk    = (const float*)d_in[7];
    const float* Wv    = (const float*)d_in[8];
    const float* bv    = (const float*)d_in[9];
    const float* Wo    = (const float*)d_in[10];
    const float* bo    = (const float*)d_in[11];
    const float* gamma = (const float*)d_in[12];
    const float* beta  = (const float*)d_in[13];

    float* out  = (float*)d_out;
    float* attn = out + (size_t)M_TOT * D_MODEL;

    uint16_t *inqh, *inql, *inkh, *inkl, *invh, *invl;
    uint16_t *wqh, *wql, *wkh, *wkl, *wvh, *wvl, *woh, *wol;
    uint16_t *Qh, *Ql, *Kh, *Kl, *Vh, *Vl, *Oh, *Ol, *Eh, *El;
    float *Pp, *rsp;
    cudaGetSymbolAddress((void**)&inqh, g_inqh); cudaGetSymbolAddress((void**)&inql, g_inql);
    cudaGetSymbolAddress((void**)&inkh, g_inkh); cudaGetSymbolAddress((void**)&inkl, g_inkl);
    cudaGetSymbolAddress((void**)&invh, g_invh); cudaGetSymbolAddress((void**)&invl, g_invl);
    cudaGetSymbolAddress((void**)&wqh, g_wqh); cudaGetSymbolAddress((void**)&wql, g_wql);
    cudaGetSymbolAddress((void**)&wkh, g_wkh); cudaGetSymbolAddress((void**)&wkl, g_wkl);
    cudaGetSymbolAddress((void**)&wvh, g_wvh); cudaGetSymbolAddress((void**)&wvl, g_wvl);
    cudaGetSymbolAddress((void**)&woh, g_woh); cudaGetSymbolAddress((void**)&wol, g_wol);
    cudaGetSymbolAddress((void**)&Qh, g_Qh); cudaGetSymbolAddress((void**)&Ql, g_Ql);
    cudaGetSymbolAddress((void**)&Kh, g_Kh); cudaGetSymbolAddress((void**)&Kl, g_Kl);
    cudaGetSymbolAddress((void**)&Vh, g_Vh); cudaGetSymbolAddress((void**)&Vl, g_Vl);
    cudaGetSymbolAddress((void**)&Oh, g_Oh); cudaGetSymbolAddress((void**)&Ol, g_Ol);
    cudaGetSymbolAddress((void**)&Eh, g_Eh); cudaGetSymbolAddress((void**)&El, g_El);
    cudaGetSymbolAddress((void**)&Pp, g_P);
    cudaGetSymbolAddress((void**)&rsp, g_rs);

    const int SMEM_GEMM   = 81920;
    const int SMEM_SCORES = 73728;
    cudaFuncSetAttribute(gemm_s<true>,  cudaFuncAttributeMaxDynamicSharedMemorySize, SMEM_GEMM);
    cudaFuncSetAttribute(gemm_s<false>, cudaFuncAttributeMaxDynamicSharedMemorySize, SMEM_GEMM);
    cudaFuncSetAttribute(scores_exp,    cudaFuncAttributeMaxDynamicSharedMemorySize, SMEM_SCORES);

    // init: rowsums + masked attn region
    zero_rs_kernel<<<48, 256>>>((float4*)rsp);
    dim3 gTiles(S_ / 128, S_ / 128, BH_);
    zerofill_kernel<<<gTiles, 256>>>(attn);

    // pre-split inputs + weights
    split_kernel<<<3072, 256>>>((const float4*)q, (uint2*)inqh, (uint2*)inql);
    split_kernel<<<3072, 256>>>((const float4*)k, (uint2*)inkh, (uint2*)inkl);
    split_kernel<<<3072, 256>>>((const float4*)v, (uint2*)invh, (uint2*)invl);
    split_kernel<<<576, 256>>>((const float4*)Wq, (uint2*)wqh, (uint2*)wql);
    split_kernel<<<576, 256>>>((const float4*)Wk, (uint2*)wkh, (uint2*)wkl);
    split_kernel<<<576, 256>>>((const float4*)Wv, (uint2*)wvh, (uint2*)wvl);
    split_kernel<<<576, 256>>>((const float4*)Wo, (uint2*)woh, (uint2*)wol);

    dim3 gProj(M_TOT / 128, D_MODEL / 128);
    gemm_s<true><<<gProj, 256, SMEM_GEMM>>>(inqh, inql, wqh, wql, bq, Qh, Ql, nullptr);
    gemm_s<true><<<gProj, 256, SMEM_GEMM>>>(inkh, inkl, wkh, wkl, bk, Kh, Kl, nullptr);
    gemm_s<true><<<gProj, 256, SMEM_GEMM>>>(invh, invl, wvh, wvl, bv, Vh, Vl, nullptr);

    scores_exp<<<gTiles, 256, SMEM_SCORES>>>(Qh, Ql, Kh, Kl, Eh, El, rsp);

    dim3 gPV(S_ / 128, BH_);
    pv_s<<<gPV, 256>>>(Eh, El, rsp, Vh, Vl, attn, Oh, Ol);

    gemm_s<false><<<gProj, 256, SMEM_GEMM>>>(Oh, Ol, woh, wol, bo, nullptr, nullptr, Pp);

    ln_kernel<<<M_TOT, 192>>>(q, Pp, gamma, beta, out);
}

// round 8
// speedup vs baseline: 1.2227x; 1.2227x over previous
#include <cuda_runtime.h>
#include <cuda_bf16.h>
#include <math.h>
#include <stdint.h>

#define D_MODEL 768
#define N_HEADS 12
#define D_KH    64
#define B_      2
#define S_      2048
#define M_TOT   (B_ * S_)
#define BH_     (B_ * N_HEADS)
#define LN_EPS  1e-5f
#define NELEM   ((size_t)M_TOT * D_MODEL)
#define WELEM   ((size_t)D_MODEL * D_MODEL)

// ---------------- scratch (allocation-free: __device__ globals) ----------------
__device__ uint16_t g_inqh[NELEM], g_inql[NELEM];
__device__ uint16_t g_inkh[NELEM], g_inkl[NELEM];
__device__ uint16_t g_invh[NELEM], g_invl[NELEM];
__device__ uint16_t g_wqh[WELEM], g_wql[WELEM];
__device__ uint16_t g_wkh[WELEM], g_wkl[WELEM];
__device__ uint16_t g_wvh[WELEM], g_wvl[WELEM];
__device__ uint16_t g_woh[WELEM], g_wol[WELEM];
__device__ uint16_t g_Qh[NELEM], g_Ql[NELEM];
__device__ uint16_t g_Kh[NELEM], g_Kl[NELEM];
__device__ uint16_t g_Vh[NELEM], g_Vl[NELEM];
__device__ uint16_t g_Oh[NELEM], g_Ol[NELEM];
__device__ float    g_P[NELEM];

// ======================= helpers =======================
__device__ __forceinline__ uint32_t smem_u32(const void* p) {
    uint32_t a;
    asm("{ .reg .u64 t; cvta.to.shared.u64 t, %1; cvt.u32.u64 %0, t; }"
        : "=r"(a) : "l"(p));
    return a;
}
__device__ __forceinline__ void ldm_x4(uint32_t* r, uint32_t addr) {
    asm volatile("ldmatrix.sync.aligned.m8n8.x4.shared.b16 {%0,%1,%2,%3}, [%4];"
                 : "=r"(r[0]), "=r"(r[1]), "=r"(r[2]), "=r"(r[3]) : "r"(addr));
}
__device__ __forceinline__ void ldm_x2(uint32_t* r, uint32_t addr) {
    asm volatile("ldmatrix.sync.aligned.m8n8.x2.shared.b16 {%0,%1}, [%2];"
                 : "=r"(r[0]), "=r"(r[1]) : "r"(addr));
}
__device__ __forceinline__ void ldm_x2_trans(uint32_t* r, uint32_t addr) {
    asm volatile("ldmatrix.sync.aligned.m8n8.x2.trans.shared.b16 {%0,%1}, [%2];"
                 : "=r"(r[0]), "=r"(r[1]) : "r"(addr));
}
__device__ __forceinline__ void mma_bf16(float* c, const uint32_t* a, const uint32_t* b) {
    asm volatile(
        "mma.sync.aligned.m16n8k16.row.col.f32.bf16.bf16.f32 "
        "{%0,%1,%2,%3}, {%4,%5,%6,%7}, {%8,%9}, {%0,%1,%2,%3};"
        : "+f"(c[0]), "+f"(c[1]), "+f"(c[2]), "+f"(c[3])
        : "r"(a[0]), "r"(a[1]), "r"(a[2]), "r"(a[3]), "r"(b[0]), "r"(b[1]));
}
__device__ __forceinline__ void cp16(uint32_t s, const void* g) {
    asm volatile("cp.async.cg.shared.global [%0], [%1], 16;" :: "r"(s), "l"(g));
}
#define CP_COMMIT() asm volatile("cp.async.commit_group;")
#define CP_WAIT0()  asm volatile("cp.async.wait_group 0;")
#define CP_WAIT1()  asm volatile("cp.async.wait_group 1;")

__device__ __forceinline__ uint32_t pack2(__nv_bfloat16 a, __nv_bfloat16 b) {
    return ((uint32_t)__bfloat16_as_ushort(b) << 16) | (uint32_t)__bfloat16_as_ushort(a);
}
__device__ __forceinline__ void split4(float4 v, uint2& hi, uint2& lo) {
    __nv_bfloat16 h0 = __float2bfloat16(v.x), h1 = __float2bfloat16(v.y);
    __nv_bfloat16 h2 = __float2bfloat16(v.z), h3 = __float2bfloat16(v.w);
    hi = make_uint2(pack2(h0, h1), pack2(h2, h3));
    __nv_bfloat16 l0 = __float2bfloat16(v.x - __bfloat162float(h0));
    __nv_bfloat16 l1 = __float2bfloat16(v.y - __bfloat162float(h1));
    __nv_bfloat16 l2 = __float2bfloat16(v.z - __bfloat162float(h2));
    __nv_bfloat16 l3 = __float2bfloat16(v.w - __bfloat162float(h3));
    lo = make_uint2(pack2(l0, l1), pack2(l2, l3));
}
__device__ __forceinline__ void split2(float x, float y, uint32_t& hi, uint32_t& lo) {
    __nv_bfloat16 h0 = __float2bfloat16(x), h1 = __float2bfloat16(y);
    hi = pack2(h0, h1);
    lo = pack2(__float2bfloat16(x - __bfloat162float(h0)),
               __float2bfloat16(y - __bfloat162float(h1)));
}

// ======================= by-value arg structs (graph-safe) =======================
struct SplitArgs {
    const float4* in[4];
    uint2* hi[4];
    uint2* lo[4];
};
struct Gemm3Args {
    const uint16_t* Ah[3];
    const uint16_t* Al[3];
    const uint16_t* Wh[3];
    const uint16_t* Wl[3];
    const float*    bias[3];
    uint16_t*       Ch[3];
    uint16_t*       Cl[3];
};

// fused split: blockIdx.y selects the tensor
__global__ void split_fused_kernel(SplitArgs a)
{
    const int z = blockIdx.y;
    int i = blockIdx.x * 256 + threadIdx.x;
    uint2 h, l;
    split4(a.in[z][i], h, l);
    a.hi[z][i] = h; a.lo[z][i] = l;
}

#define LDA 40
#define LDV 72

// =====================================================================
// GEMM (NT): C = A @ W^T + bias, 2-stage cp.async pipeline, split-bf16.
// FUSED3: z = blockIdx.z selects operand set; writes split bf16.
// else: single GEMM writing fp32 Cf.
// =====================================================================
template<bool FUSED3>
__global__ void __launch_bounds__(256)
gemm_s(Gemm3Args ga,
       const uint16_t* __restrict__ Ahg_, const uint16_t* __restrict__ Alg_,
       const uint16_t* __restrict__ Whg_, const uint16_t* __restrict__ Wlg_,
       const float* __restrict__ bias_, float* __restrict__ Cf)
{
    const uint16_t *Ahg, *Alg, *Whg, *Wlg;
    const float* bias;
    uint16_t *Ch = nullptr, *Cl = nullptr;
    if (FUSED3) {
        const int z = blockIdx.z;
        Ahg = ga.Ah[z]; Alg = ga.Al[z];
        Whg = ga.Wh[z]; Wlg = ga.Wl[z];
        bias = ga.bias[z]; Ch = ga.Ch[z]; Cl = ga.Cl[z];
    } else {
        Ahg = Ahg_; Alg = Alg_; Whg = Whg_; Wlg = Wlg_;
        bias = bias_;
    }

    extern __shared__ __align__(16) char sm[];
    const uint32_t sb = smem_u32(sm);
    const int tid = threadIdx.x, wid = tid >> 5, lane = tid & 31;
    const int m0 = blockIdx.x * 128, n0 = blockIdx.y * 128;
    const int wm = (wid & 1) * 64, wn = (wid >> 1) * 32;

    float acc[4][4][4] = {};
    {
        #pragma unroll
        for (int i = 0; i < 2; i++) {
            int f = tid + i * 256;
            int r = f >> 2, c8 = (f & 3) * 8;
            uint32_t so = sb + (uint32_t)(r * LDA + c8) * 2;
            size_t ga2 = (size_t)(m0 + r) * 768 + c8;
            size_t gb = (size_t)(n0 + r) * 768 + c8;
            cp16(so,          Ahg + ga2);
            cp16(so + 10240u, Alg + ga2);
            cp16(so + 20480u, Whg + gb);
            cp16(so + 30720u, Wlg + gb);
        }
        CP_COMMIT();
    }
    for (int c = 0; c < 24; c++) {
        const int st = c & 1;
        if (c < 23) {
            const int k0 = (c + 1) * 32;
            const uint32_t stb = sb + (uint32_t)(st ^ 1) * 40960u;
            #pragma unroll
            for (int i = 0; i < 2; i++) {
                int f = tid + i * 256;
                int r = f >> 2, c8 = (f & 3) * 8;
                uint32_t so = stb + (uint32_t)(r * LDA + c8) * 2;
                size_t ga2 = (size_t)(m0 + r) * 768 + k0 + c8;
                size_t gb = (size_t)(n0 + r) * 768 + k0 + c8;
                cp16(so,          Ahg + ga2);
                cp16(so + 10240u, Alg + ga2);
                cp16(so + 20480u, Whg + gb);
                cp16(so + 30720u, Wlg + gb);
            }
            CP_COMMIT();
            CP_WAIT1();
        } else {
            CP_WAIT0();
        }
        __syncthreads();
        const uint32_t base = sb + (uint32_t)st * 40960u;
        #pragma unroll
        for (int ks = 0; ks < 2; ks++) {
            uint32_t ah[4][4], al[4][4];
            const int arow = wm + (lane & 7) + ((lane >> 3) & 1) * 8;
            const int acol = ks * 16 + (lane >> 4) * 8;
            #pragma unroll
            for (int mt = 0; mt < 4; mt++) {
                uint32_t off = (uint32_t)((arow + mt * 16) * LDA + acol) * 2;
                ldm_x4(ah[mt], base + off);
                ldm_x4(al[mt], base + 10240u + off);
            }
            const int brow = wn + (lane & 7);
            const int bcol = ks * 16 + ((lane >> 3) & 1) * 8;
            #pragma unroll
            for (int nt = 0; nt < 4; nt++) {
                uint32_t off = (uint32_t)((brow + nt * 8) * LDA + bcol) * 2;
                uint32_t bh2[2], bl2[2];
                ldm_x2(bh2, base + 20480u + off);
                ldm_x2(bl2, base + 30720u + off);
                #pragma unroll
                for (int mt = 0; mt < 4; mt++) {
                    mma_bf16(acc[mt][nt], ah[mt], bh2);
                    mma_bf16(acc[mt][nt], ah[mt], bl2);
                    mma_bf16(acc[mt][nt], al[mt], bh2);
                }
            }
        }
        __syncthreads();
    }
    #pragma unroll
    for (int mt = 0; mt < 4; mt++) {
        const int m = m0 + wm + mt * 16 + (lane >> 2);
        #pragma unroll
        for (int nt = 0; nt < 4; nt++) {
            const int n = n0 + wn + nt * 8 + (lane & 3) * 2;
            float2 bv = *(const float2*)&bias[n];
            float f0 = acc[mt][nt][0] + bv.x, f1 = acc[mt][nt][1] + bv.y;
            float f2 = acc[mt][nt][2] + bv.x, f3 = acc[mt][nt][3] + bv.y;
            if (FUSED3) {
                uint32_t hi, lo;
                split2(f0, f1, hi, lo);
                *(uint32_t*)&Ch[(size_t)m * 768 + n] = hi;
                *(uint32_t*)&Cl[(size_t)m * 768 + n] = lo;
                split2(f2, f3, hi, lo);
                *(uint32_t*)&Ch[(size_t)(m + 8) * 768 + n] = hi;
                *(uint32_t*)&Cl[(size_t)(m + 8) * 768 + n] = lo;
            } else {
                *(float2*)&Cf[(size_t)m * 768 + n]       = make_float2(f0, f1);
                *(float2*)&Cf[(size_t)(m + 8) * 768 + n] = make_float2(f2, f3);
            }
        }
    }
}

// =====================================================================
// Scores: attn = 0.125 * Q.K^T for kt<=qt; zeros else.
// =====================================================================
__global__ void __launch_bounds__(256)
scores_s(const uint16_t* __restrict__ Qh, const uint16_t* __restrict__ Ql,
         const uint16_t* __restrict__ Kh, const uint16_t* __restrict__ Kl,
         float* __restrict__ attn)
{
    const int qt = blockIdx.x, kt = blockIdx.y, bh = blockIdx.z;
    const int q0 = qt * 128, k0 = kt * 128;
    const int tid = threadIdx.x;

    if (kt > qt) {
        float4 z = make_float4(0.f, 0.f, 0.f, 0.f);
        float4* o4 = (float4*)(attn + ((size_t)bh * S_ + q0) * S_ + k0);
        #pragma unroll
        for (int i = 0; i < 16; i++) {
            int f = tid + i * 256;
            int r = f >> 5, c = f & 31;
            o4[(size_t)r * (S_ / 4) + c] = z;
        }
        return;
    }

    extern __shared__ __align__(16) char sm[];
    const uint32_t sb = smem_u32(sm);
    const int wid = tid >> 5, lane = tid & 31;
    const int b = bh / N_HEADS, h = bh % N_HEADS;
    const int wm = (wid & 1) * 64, wn = (wid >> 1) * 32;
    const size_t qbase = (size_t)(b * S_ + q0) * 768 + h * 64;
    const size_t kbase = (size_t)(b * S_ + k0) * 768 + h * 64;

    #pragma unroll
    for (int i = 0; i < 4; i++) {
        int f = tid + i * 256;
        int r = f >> 3, c8 = (f & 7) * 8;
        uint32_t so = sb + (uint32_t)(r * LDV + c8) * 2;
        size_t gq = qbase + (size_t)r * 768 + c8;
        size_t gk = kbase + (size_t)r * 768 + c8;
        cp16(so,          Qh + gq);
        cp16(so + 18432u, Ql + gq);
        cp16(so + 36864u, Kh + gk);
        cp16(so + 55296u, Kl + gk);
    }
    CP_COMMIT(); CP_WAIT0();
    __syncthreads();

    float acc[4][4][4] = {};
    #pragma unroll
    for (int ks = 0; ks < 4; ks++) {
        uint32_t ah[4][4], al[4][4];
        const int arow = wm + (lane & 7) + ((lane >> 3) & 1) * 8;
        const int acol = ks * 16 + (lane >> 4) * 8;
        #pragma unroll
        for (int mt = 0; mt < 4; mt++) {
            uint32_t off = (uint32_t)((arow + mt * 16) * LDV + acol) * 2;
            ldm_x4(ah[mt], sb + off);
            ldm_x4(al[mt], sb + 18432u + off);
        }
        const int brow = wn + (lane & 7);
        const int bcol = ks * 16 + ((lane >> 3) & 1) * 8;
        #pragma unroll
        for (int nt = 0; nt < 4; nt++) {
            uint32_t off = (uint32_t)((brow + nt * 8) * LDV + bcol) * 2;
            uint32_t bh2[2], bl2[2];
            ldm_x2(bh2, sb + 36864u + off);
            ldm_x2(bl2, sb + 55296u + off);
            #pragma unroll
            for (int mt = 0; mt < 4; mt++) {
                mma_bf16(acc[mt][nt], ah[mt], bh2);
                mma_bf16(acc[mt][nt], ah[mt], bl2);
                mma_bf16(acc[mt][nt], al[mt], bh2);
            }
        }
    }
    #pragma unroll
    for (int mt = 0; mt < 4; mt++) {
        const int qrow = q0 + wm + mt * 16 + (lane >> 2);
        #pragma unroll
        for (int nt = 0; nt < 4; nt++) {
            const int kcol = k0 + wn + nt * 8 + (lane & 3) * 2;
            float* op0 = attn + ((size_t)bh * S_ + qrow) * S_ + kcol;
            float* op1 = attn + ((size_t)bh * S_ + qrow + 8) * S_ + kcol;
            *(float2*)op0 = make_float2(acc[mt][nt][0] * 0.125f, acc[mt][nt][1] * 0.125f);
            *(float2*)op1 = make_float2(acc[mt][nt][2] * 0.125f, acc[mt][nt][3] * 0.125f);
        }
    }
}

// =====================================================================
// Row softmax over cols [0, (qt+1)*128); causal mask inside.
// =====================================================================
__global__ void softmax_kernel(float* __restrict__ attn)
{
    const int q  = blockIdx.x;
    const int bh = blockIdx.y;
    const int n4 = ((q >> 7) + 1) * 32;
    float4* row4 = (float4*)(attn + ((size_t)bh * S_ + q) * S_);
    const int tid = threadIdx.x;
    const int lane = tid & 31, wid = tid >> 5;
    __shared__ float red[8];

    float4 v[2];
    int cnt = 0;
    float m = -INFINITY;
    for (int i = tid; i < n4; i += 256) {
        float4 t = row4[i];
        int c = i * 4;
        t.x = (c + 0 <= q) ? t.x : -INFINITY;
        t.y = (c + 1 <= q) ? t.y : -INFINITY;
        t.z = (c + 2 <= q) ? t.z : -INFINITY;
        t.w = (c + 3 <= q) ? t.w : -INFINITY;
        m = fmaxf(m, fmaxf(fmaxf(t.x, t.y), fmaxf(t.z, t.w)));
        v[cnt++] = t;
    }
    #pragma unroll
    for (int s = 16; s > 0; s >>= 1)
        m = fmaxf(m, __shfl_xor_sync(0xffffffff, m, s));
    if (lane == 0) red[wid] = m;
    __syncthreads();
    m = fmaxf(fmaxf(fmaxf(red[0], red[1]), fmaxf(red[2], red[3])),
              fmaxf(fmaxf(red[4], red[5]), fmaxf(red[6], red[7])));
    __syncthreads();

    float sum = 0.f;
    for (int j = 0; j < cnt; j++) {
        float4 t = v[j];
        t.x = __expf(t.x - m); t.y = __expf(t.y - m);
        t.z = __expf(t.z - m); t.w = __expf(t.w - m);
        sum += t.x + t.y + t.z + t.w;
        v[j] = t;
    }
    #pragma unroll
    for (int s = 16; s > 0; s >>= 1)
        sum += __shfl_xor_sync(0xffffffff, sum, s);
    if (lane == 0) red[wid] = sum;
    __syncthreads();
    sum = red[0] + red[1] + red[2] + red[3] + red[4] + red[5] + red[6] + red[7];
    const float inv = 1.0f / sum;

    for (int j = 0; j < cnt; j++) {
        float4 t = v[j];
        t.x *= inv; t.y *= inv; t.z *= inv; t.w *= inv;
        row4[tid + j * 256] = t;
    }
}

// =====================================================================
// PV: O = P @ V, register-prefetched P, double-buffered cp.async V.
// =====================================================================
__global__ void __launch_bounds__(256)
pv_s(const float* __restrict__ attn,
     const uint16_t* __restrict__ Vhg, const uint16_t* __restrict__ Vlg,
     uint16_t* __restrict__ Oh, uint16_t* __restrict__ Ol)
{
    __shared__ __align__(16) uint16_t Ph[128][LDA], Pl[128][LDA];
    __shared__ __align__(16) uint16_t Vh_s[2][32][LDV], Vl_s[2][32][LDV];
    const int tid = threadIdx.x, wid = tid >> 5, lane = tid & 31;
    const int qt = gridDim.x - 1 - blockIdx.x;
    const int bh = blockIdx.y;
    const int b = bh / N_HEADS, h = bh % N_HEADS;
    const int q0 = qt * 128;
    const int wm = (wid & 3) * 32, wn = (wid >> 2) * 32;
    const uint32_t pHb = smem_u32(Ph), pLb = smem_u32(Pl);

    const float* Arow = attn + ((size_t)bh * S_ + q0) * S_;
    const size_t vbase = (size_t)(b * S_) * 768 + h * 64;
    const int vr = tid >> 3, vc8 = (tid & 7) * 8;
    const uint32_t vso = (uint32_t)(vr * LDV + vc8) * 2;

    float acc[2][4][4] = {};
    const int n_chunks = 4 * (qt + 1);
    const int prow = tid >> 1, pc4 = (tid & 1) * 16;

    {
        size_t gv = vbase + (size_t)vr * 768 + vc8;
        cp16(smem_u32(Vh_s[0]) + vso, Vhg + gv);
        cp16(smem_u32(Vl_s[0]) + vso, Vlg + gv);
        CP_COMMIT();
    }
    float4 preg[4];
    #pragma unroll
    for (int j = 0; j < 4; j++)
        preg[j] = *(const float4*)&Arow[(size_t)prow * S_ + pc4 + j * 4];

    for (int c = 0; c < n_chunks; c++) {
        const int st = c & 1;
        #pragma unroll
        for (int j = 0; j < 4; j++) {
            uint2 hi, lo;
            split4(preg[j], hi, lo);
            *(uint2*)&Ph[prow][pc4 + j * 4] = hi;
            *(uint2*)&Pl[prow][pc4 + j * 4] = lo;
        }
        if (c + 1 < n_chunks) {
            size_t gv = vbase + (size_t)((c + 1) * 32 + vr) * 768 + vc8;
            cp16(smem_u32(Vh_s[st ^ 1]) + vso, Vhg + gv);
            cp16(smem_u32(Vl_s[st ^ 1]) + vso, Vlg + gv);
            CP_COMMIT();
            CP_WAIT1();
        } else {
            CP_WAIT0();
        }
        __syncthreads();
        if (c + 1 < n_chunks) {
            const int k0n = (c + 1) * 32;
            #pragma unroll
            for (int j = 0; j < 4; j++)
                preg[j] = *(const float4*)&Arow[(size_t)prow * S_ + k0n + pc4 + j * 4];
        }
        const uint32_t vHb = smem_u32(Vh_s[st]);
        const uint32_t vLb = smem_u32(Vl_s[st]);
        #pragma unroll
        for (int ks = 0; ks < 2; ks++) {
            uint32_t ph[2][4], pl[2][4];
            const int arow = wm + (lane & 7) + ((lane >> 3) & 1) * 8;
            const int acol = ks * 16 + (lane >> 4) * 8;
            #pragma unroll
            for (int mt = 0; mt < 2; mt++) {
                uint32_t off = (uint32_t)((arow + mt * 16) * LDA + acol) * 2;
                ldm_x4(ph[mt], pHb + off);
                ldm_x4(pl[mt], pLb + off);
            }
            const int krow = ks * 16 + ((lane >> 3) & 1) * 8 + (lane & 7);
            #pragma unroll
            for (int nt = 0; nt < 4; nt++) {
                uint32_t off = (uint32_t)(krow * LDV + wn + nt * 8) * 2;
                uint32_t vh2[2], vl2[2];
                ldm_x2_trans(vh2, vHb + off);
                ldm_x2_trans(vl2, vLb + off);
                #pragma unroll
                for (int mt = 0; mt < 2; mt++) {
                    mma_bf16(acc[mt][nt], ph[mt], vh2);
                    mma_bf16(acc[mt][nt], ph[mt], vl2);
                    mma_bf16(acc[mt][nt], pl[mt], vh2);
                }
            }
        }
        __syncthreads();
    }
    #pragma unroll
    for (int mt = 0; mt < 2; mt++) {
        const int qrow = q0 + wm + mt * 16 + (lane >> 2);
        const size_t r0 = (size_t)(b * S_ + qrow) * 768 + h * 64;
        const size_t r1 = (size_t)(b * S_ + qrow + 8) * 768 + h * 64;
        #pragma unroll
        for (int nt = 0; nt < 4; nt++) {
            const int n = wn + nt * 8 + (lane & 3) * 2;
            uint32_t hi, lo;
            split2(acc[mt][nt][0], acc[mt][nt][1], hi, lo);
            *(uint32_t*)&Oh[r0 + n] = hi;
            *(uint32_t*)&Ol[r0 + n] = lo;
            split2(acc[mt][nt][2], acc[mt][nt][3], hi, lo);
            *(uint32_t*)&Oh[r1 + n] = hi;
            *(uint32_t*)&Ol[r1 + n] = lo;
        }
    }
}

// =====================================================================
// Residual + LayerNorm, float4, 192 threads.
// =====================================================================
__global__ void ln_kernel(const float* __restrict__ resid,
                          const float* __restrict__ P,
                          const float* __restrict__ gamma,
                          const float* __restrict__ beta,
                          float* __restrict__ out)
{
    const int m = blockIdx.x;
    const int tid = threadIdx.x;
    const int lane = tid & 31, wid = tid >> 5;
    __shared__ float red[6];

    const float4* r4 = (const float4*)(resid + (size_t)m * D_MODEL);
    const float4* p4 = (const float4*)(P + (size_t)m * D_MODEL);
    float4 a = r4[tid], b = p4[tid];
    float4 x = make_float4(a.x + b.x, a.y + b.y, a.z + b.z, a.w + b.w);

    float s = x.x + x.y + x.z + x.w;
    #pragma unroll
    for (int sh = 16; sh > 0; sh >>= 1)
        s += __shfl_xor_sync(0xffffffff, s, sh);
    if (lane == 0) red[wid] = s;
    __syncthreads();
    s = red[0] + red[1] + red[2] + red[3] + red[4] + red[5];
    const float mu = s * (1.0f / D_MODEL);
    __syncthreads();

    float4 d = make_float4(x.x - mu, x.y - mu, x.z - mu, x.w - mu);
    float v = d.x * d.x + d.y * d.y + d.z * d.z + d.w * d.w;
    #pragma unroll
    for (int sh = 16; sh > 0; sh >>= 1)
        v += __shfl_xor_sync(0xffffffff, v, sh);
    if (lane == 0) red[wid] = v;
    __syncthreads();
    v = red[0] + red[1] + red[2] + red[3] + red[4] + red[5];
    const float rstd = rsqrtf(v * (1.0f / D_MODEL) + LN_EPS);

    float4 g = ((const float4*)gamma)[tid];
    float4 be = ((const float4*)beta)[tid];
    float4 o = make_float4(d.x * rstd * g.x + be.x,
                           d.y * rstd * g.y + be.y,
                           d.z * rstd * g.z + be.z,
                           d.w * rstd * g.w + be.w);
    ((float4*)(out + (size_t)m * D_MODEL))[tid] = o;
}

// =====================================================================
extern "C" void kernel_launch(void* const* d_in, const int* in_sizes, int n_in,
                              void* d_out, int out_size)
{
    const float* q     = (const float*)d_in[0];
    const float* k     = (const float*)d_in[1];
    const float* v     = (const float*)d_in[2];
    const float* Wq    = (const float*)d_in[4];
    const float* bq    = (const float*)d_in[5];
    const float* Wk    = (const float*)d_in[6];
    const float* bk    = (const float*)d_in[7];
    const float* Wv    = (const float*)d_in[8];
    const float* bv    = (const float*)d_in[9];
    const float* Wo    = (const float*)d_in[10];
    const float* bo    = (const float*)d_in[11];
    const float* gamma = (const float*)d_in[12];
    const float* beta  = (const float*)d_in[13];

    float* out  = (float*)d_out;
    float* attn = out + (size_t)M_TOT * D_MODEL;

    uint16_t *inqh, *inql, *inkh, *inkl, *invh, *invl;
    uint16_t *wqh, *wql, *wkh, *wkl, *wvh, *wvl, *woh, *wol;
    uint16_t *Qh, *Ql, *Kh, *Kl, *Vh, *Vl, *Oh, *Ol;
    float* Pp;
    cudaGetSymbolAddress((void**)&inqh, g_inqh); cudaGetSymbolAddress((void**)&inql, g_inql);
    cudaGetSymbolAddress((void**)&inkh, g_inkh); cudaGetSymbolAddress((void**)&inkl, g_inkl);
    cudaGetSymbolAddress((void**)&invh, g_invh); cudaGetSymbolAddress((void**)&invl, g_invl);
    cudaGetSymbolAddress((void**)&wqh, g_wqh); cudaGetSymbolAddress((void**)&wql, g_wql);
    cudaGetSymbolAddress((void**)&wkh, g_wkh); cudaGetSymbolAddress((void**)&wkl, g_wkl);
    cudaGetSymbolAddress((void**)&wvh, g_wvh); cudaGetSymbolAddress((void**)&wvl, g_wvl);
    cudaGetSymbolAddress((void**)&woh, g_woh); cudaGetSymbolAddress((void**)&wol, g_wol);
    cudaGetSymbolAddress((void**)&Qh, g_Qh); cudaGetSymbolAddress((void**)&Ql, g_Ql);
    cudaGetSymbolAddress((void**)&Kh, g_Kh); cudaGetSymbolAddress((void**)&Kl, g_Kl);
    cudaGetSymbolAddress((void**)&Vh, g_Vh); cudaGetSymbolAddress((void**)&Vl, g_Vl);
    cudaGetSymbolAddress((void**)&Oh, g_Oh); cudaGetSymbolAddress((void**)&Ol, g_Ol);
    cudaGetSymbolAddress((void**)&Pp, g_P);

    const int SMEM_GEMM   = 81920;
    const int SMEM_SCORES = 73728;
    cudaFuncSetAttribute(gemm_s<true>,  cudaFuncAttributeMaxDynamicSharedMemorySize, SMEM_GEMM);
    cudaFuncSetAttribute(gemm_s<false>, cudaFuncAttributeMaxDynamicSharedMemorySize, SMEM_GEMM);
    cudaFuncSetAttribute(scores_s,      cudaFuncAttributeMaxDynamicSharedMemorySize, SMEM_SCORES);

    // fused pre-split of inputs (3 x 3072 blocks)
    SplitArgs sa_in;
    sa_in.in[0] = (const float4*)q; sa_in.hi[0] = (uint2*)inqh; sa_in.lo[0] = (uint2*)inql;
    sa_in.in[1] = (const float4*)k; sa_in.hi[1] = (uint2*)inkh; sa_in.lo[1] = (uint2*)inkl;
    sa_in.in[2] = (const float4*)v; sa_in.hi[2] = (uint2*)invh; sa_in.lo[2] = (uint2*)invl;
    sa_in.in[3] = nullptr; sa_in.hi[3] = nullptr; sa_in.lo[3] = nullptr;
    split_fused_kernel<<<dim3(3072, 3), 256>>>(sa_in);

    // fused pre-split of weights (4 x 576 blocks)
    SplitArgs sa_w;
    sa_w.in[0] = (const float4*)Wq; sa_w.hi[0] = (uint2*)wqh; sa_w.lo[0] = (uint2*)wql;
    sa_w.in[1] = (const float4*)Wk; sa_w.hi[1] = (uint2*)wkh; sa_w.lo[1] = (uint2*)wkl;
    sa_w.in[2] = (const float4*)Wv; sa_w.hi[2] = (uint2*)wvh; sa_w.lo[2] = (uint2*)wvl;
    sa_w.in[3] = (const float4*)Wo; sa_w.hi[3] = (uint2*)woh; sa_w.lo[3] = (uint2*)wol;
    split_fused_kernel<<<dim3(576, 4), 256>>>(sa_w);

    // fused QKV projections
    Gemm3Args ga;
    ga.Ah[0] = inqh; ga.Al[0] = inql; ga.Wh[0] = wqh; ga.Wl[0] = wql;
    ga.bias[0] = bq; ga.Ch[0] = Qh; ga.Cl[0] = Ql;
    ga.Ah[1] = inkh; ga.Al[1] = inkl; ga.Wh[1] = wkh; ga.Wl[1] = wkl;
    ga.bias[1] = bk; ga.Ch[1] = Kh; ga.Cl[1] = Kl;
    ga.Ah[2] = invh; ga.Al[2] = invl; ga.Wh[2] = wvh; ga.Wl[2] = wvl;
    ga.bias[2] = bv; ga.Ch[2] = Vh; ga.Cl[2] = Vl;
    dim3 gProj3(M_TOT / 128, D_MODEL / 128, 3);
    gemm_s<true><<<gProj3, 256, SMEM_GEMM>>>(ga, nullptr, nullptr, nullptr, nullptr,
                                             nullptr, nullptr);

    dim3 gScores(S_ / 128, S_ / 128, BH_);
    scores_s<<<gScores, 256, SMEM_SCORES>>>(Qh, Ql, Kh, Kl, attn);

    dim3 gSoft(S_, BH_);
    softmax_kernel<<<gSoft, 256>>>(attn);

    dim3 gPV(S_ / 128, BH_);
    pv_s<<<gPV, 256>>>(attn, Vh, Vl, Oh, Ol);

    Gemm3Args ga_dummy = {};
    dim3 gProj(M_TOT / 128, D_MODEL / 128);
    gemm_s<false><<<gProj, 256, SMEM_GEMM>>>(ga_dummy, Oh, Ol, woh, wol, bo, Pp);

    ln_kernel<<<M_TOT, 192>>>(q, Pp, gamma, beta, out);
}